// round 3
// baseline (speedup 1.0000x reference)
#include <cuda_runtime.h>
#include <math.h>

#define NN 100000
#define NE 1600000
#define IND 128
#define HID 64
#define NC 40

// Ping-pong scratch (25.6 MB each) — allocation-free per harness rules.
__device__ float g_bufA[(size_t)NN * HID];
__device__ float g_bufB[(size_t)NN * HID];

// ---------------------------------------------------------------------------
// Zero-fill (float4 stores)
// ---------------------------------------------------------------------------
__global__ __launch_bounds__(256) void zero_kernel(float* __restrict__ p, int n4) {
    int i = blockIdx.x * 256 + threadIdx.x;
    if (i < n4) reinterpret_cast<float4*>(p)[i] = make_float4(0.f, 0.f, 0.f, 0.f);
}

// ---------------------------------------------------------------------------
// C[NN,64] = act(A)[NN,K] @ W[K,64] + bias ; act = ReLU if RELU
// Block: 256 threads, tile 64 rows x 64 cols, 4x4 register blocking.
// ---------------------------------------------------------------------------
template <int K, bool RELU>
__global__ __launch_bounds__(256) void gemm64_kernel(
    const float* __restrict__ A, const float* __restrict__ W,
    const float* __restrict__ bias, float* __restrict__ C) {
    __shared__ float As[64][66];   // [row][k], padded stride to dodge conflicts
    __shared__ float Ws[64][64];   // [k][col]

    const int t  = threadIdx.x;
    const int tx = t & 15;         // col group (4 cols)
    const int ty = t >> 4;         // row group (4 rows)
    const int row0 = blockIdx.x * 64;

    float acc[4][4];
#pragma unroll
    for (int i = 0; i < 4; i++)
#pragma unroll
        for (int j = 0; j < 4; j++) acc[i][j] = 0.f;

    const int lr = t >> 4;          // 0..15
    const int lk = (t & 15) << 2;   // 0..60

    for (int kt = 0; kt < K; kt += 64) {
        // --- A tile: 64 rows x 64 k (row-major in smem) ---
#pragma unroll
        for (int i = 0; i < 4; i++) {
            int r = lr + i * 16;
            int grow = row0 + r;
            float4 v = make_float4(0.f, 0.f, 0.f, 0.f);
            if (grow < NN)
                v = *reinterpret_cast<const float4*>(A + (size_t)grow * K + kt + lk);
            if (RELU) {
                v.x = fmaxf(v.x, 0.f); v.y = fmaxf(v.y, 0.f);
                v.z = fmaxf(v.z, 0.f); v.w = fmaxf(v.w, 0.f);
            }
            As[r][lk + 0] = v.x; As[r][lk + 1] = v.y;
            As[r][lk + 2] = v.z; As[r][lk + 3] = v.w;
        }
        // --- W tile: 64 k x 64 cols, directly row-major ---
        {
            const float4* Wg = reinterpret_cast<const float4*>(W + (size_t)kt * 64);
            float4* Wsv = reinterpret_cast<float4*>(&Ws[0][0]);
#pragma unroll
            for (int i = 0; i < 4; i++) Wsv[t + i * 256] = Wg[t + i * 256];
        }
        __syncthreads();

#pragma unroll 8
        for (int k = 0; k < 64; k++) {
            float4 b = *reinterpret_cast<const float4*>(&Ws[k][tx << 2]);
            float a0 = As[(ty << 2) + 0][k];
            float a1 = As[(ty << 2) + 1][k];
            float a2 = As[(ty << 2) + 2][k];
            float a3 = As[(ty << 2) + 3][k];
            acc[0][0] += a0 * b.x; acc[0][1] += a0 * b.y; acc[0][2] += a0 * b.z; acc[0][3] += a0 * b.w;
            acc[1][0] += a1 * b.x; acc[1][1] += a1 * b.y; acc[1][2] += a1 * b.z; acc[1][3] += a1 * b.w;
            acc[2][0] += a2 * b.x; acc[2][1] += a2 * b.y; acc[2][2] += a2 * b.z; acc[2][3] += a2 * b.w;
            acc[3][0] += a3 * b.x; acc[3][1] += a3 * b.y; acc[3][2] += a3 * b.z; acc[3][3] += a3 * b.w;
        }
        __syncthreads();
    }

    float4 bv = *reinterpret_cast<const float4*>(bias + (tx << 2));
#pragma unroll
    for (int i = 0; i < 4; i++) {
        int grow = row0 + (ty << 2) + i;
        if (grow < NN) {
            float4 o = make_float4(acc[i][0] + bv.x, acc[i][1] + bv.y,
                                   acc[i][2] + bv.z, acc[i][3] + bv.w);
            *reinterpret_cast<float4*>(C + (size_t)grow * 64 + (tx << 2)) = o;
        }
    }
}

// ---------------------------------------------------------------------------
// SpMM scatter: out[row] += val * dense[col], 16 threads (x float4) per edge.
// Vector red.global.add.v4.f32 quarters atomic op count (sm_90+).
// ---------------------------------------------------------------------------
__global__ __launch_bounds__(256) void spmm_kernel(
    const int* __restrict__ er, const int* __restrict__ ec,
    const float* __restrict__ ev, const float* __restrict__ dense,
    float* __restrict__ out) {
    unsigned gid = blockIdx.x * 256u + threadIdx.x;
    unsigned e = gid >> 4;
    if (e >= NE) return;
    int c  = (gid & 15) << 2;
    int r  = __ldg(er + e);
    int cl = __ldg(ec + e);
    float v = __ldg(ev + e);
    float4 d = *reinterpret_cast<const float4*>(dense + (size_t)cl * HID + c);
    float* dst = out + (size_t)r * HID + c;
    asm volatile("red.global.add.v4.f32 [%0], {%1,%2,%3,%4};"
                 :: "l"(dst), "f"(v * d.x), "f"(v * d.y), "f"(v * d.z), "f"(v * d.w)
                 : "memory");
}

// ---------------------------------------------------------------------------
// Classifier: logits = H @ Wc + bc ; out = log_softmax(logits)
// One warp per node. Lane j handles class j and j+32 (if < 40).
// ---------------------------------------------------------------------------
__global__ __launch_bounds__(256) void cls_kernel(
    const float* __restrict__ H, const float* __restrict__ Wc,
    const float* __restrict__ bc, float* __restrict__ out) {
    __shared__ float Wcs[HID * NC];
    __shared__ float bcs[NC];
    __shared__ float hs[8][HID];

    const int t = threadIdx.x;
    for (int i = t; i < HID * NC; i += 256) Wcs[i] = Wc[i];
    if (t < NC) bcs[t] = bc[t];
    const int w = t >> 5, lane = t & 31;
    const int node = blockIdx.x * 8 + w;
    __syncthreads();

    if (node >= NN) return;

    hs[w][lane]      = H[(size_t)node * HID + lane];
    hs[w][lane + 32] = H[(size_t)node * HID + lane + 32];
    __syncwarp();

    const int j1 = lane;                 // always < 40
    const int j2 = lane + 32;            // valid iff lane < 8
    const int j2c = (j2 < NC) ? j2 : 0;

    float l1 = bcs[j1];
    float l2 = bcs[j2c];
#pragma unroll 8
    for (int k = 0; k < HID; k++) {
        float h = hs[w][k];
        l1 += h * Wcs[k * NC + j1];
        l2 += h * Wcs[k * NC + j2c];
    }
    if (j2 >= NC) l2 = -INFINITY;

    float m = fmaxf(l1, l2);
#pragma unroll
    for (int o = 16; o; o >>= 1) m = fmaxf(m, __shfl_xor_sync(0xffffffffu, m, o));
    float s = expf(l1 - m) + ((j2 < NC) ? expf(l2 - m) : 0.f);
#pragma unroll
    for (int o = 16; o; o >>= 1) s += __shfl_xor_sync(0xffffffffu, s, o);
    float lse = m + logf(s);

    out[(size_t)node * NC + j1] = l1 - lse;
    if (j2 < NC) out[(size_t)node * NC + j2] = l2 - lse;
}

// ---------------------------------------------------------------------------
extern "C" void kernel_launch(void* const* d_in, const int* in_sizes, int n_in,
                              void* d_out, int out_size) {
    const float* x  = (const float*)d_in[0];
    const int*   er = (const int*)d_in[1];
    const int*   ec = (const int*)d_in[2];
    const float* ev = (const float*)d_in[3];
    const float* W1 = (const float*)d_in[4];
    const float* b1 = (const float*)d_in[5];
    const float* W2 = (const float*)d_in[6];
    const float* b2 = (const float*)d_in[7];
    const float* Wc = (const float*)d_in[8];
    const float* bc = (const float*)d_in[9];
    float* out = (float*)d_out;

    float *bufA, *bufB;
    cudaGetSymbolAddress((void**)&bufA, g_bufA);
    cudaGetSymbolAddress((void**)&bufB, g_bufB);

    const int gemm_grid = (NN + 63) / 64;            // 1563
    const int zero_n4   = NN * HID / 4;              // 1.6M float4
    const int zero_grid = (zero_n4 + 255) / 256;     // 6250
    const int spmm_grid = (int)(((size_t)NE * 16 + 255) / 256);  // 100000
    const int cls_grid  = (NN + 7) / 8;              // 12500

    // Layer 1: support = x@W1+b1 ; h1 = spmm(support)   (relu deferred)
    gemm64_kernel<IND, false><<<gemm_grid, 256>>>(x, W1, b1, bufA);
    zero_kernel<<<zero_grid, 256>>>(bufB, zero_n4);
    spmm_kernel<<<spmm_grid, 256>>>(er, ec, ev, bufA, bufB);

    // Layer 2: support = relu(h1)@W2+b2 ; h2 = spmm(support)
    gemm64_kernel<HID, true><<<gemm_grid, 256>>>(bufB, W2, b2, bufA);
    zero_kernel<<<zero_grid, 256>>>(bufB, zero_n4);
    spmm_kernel<<<spmm_grid, 256>>>(er, ec, ev, bufA, bufB);

    // Classifier + log-softmax
    cls_kernel<<<cls_grid, 256>>>(bufB, Wc, bc, out);
}

// round 5
// speedup vs baseline: 1.3046x; 1.3046x over previous
#include <cuda_runtime.h>
#include <math.h>

#define NN 100000
#define NE 1600000
#define IND 128
#define HID 64
#define NC 40
#define SCAN_BS 1024
#define NB 98              // ceil(NN/1024)

// Scratch (allocation-free per harness rules)
__device__ float g_bufA[(size_t)NN * HID];
__device__ float g_bufB[(size_t)NN * HID];
__device__ int   g_off[NN + 1];
__device__ int   g_pos[NN];
__device__ int   g_bsum[NB];
__device__ int   g_ecol[NE];
__device__ float g_eval[NE];

// ---------------------------------------------------------------------------
// CSR build
// ---------------------------------------------------------------------------
__global__ __launch_bounds__(256) void zero_deg_kernel() {
    int i = blockIdx.x * 256 + threadIdx.x;
    if (i < NN) g_off[i] = 0;
}

__global__ __launch_bounds__(256) void hist_kernel(const int* __restrict__ er) {
    int i = blockIdx.x * 256 + threadIdx.x;
    if (i < NE) atomicAdd(&g_off[__ldg(er + i)], 1);
}

__global__ __launch_bounds__(SCAN_BS) void scan1_kernel() {
    __shared__ int s[SCAN_BS];
    int i = blockIdx.x * SCAN_BS + threadIdx.x;
    int v = (i < NN) ? g_off[i] : 0;
    s[threadIdx.x] = v;
    __syncthreads();
#pragma unroll
    for (int o = 1; o < SCAN_BS; o <<= 1) {
        int t = (threadIdx.x >= o) ? s[threadIdx.x - o] : 0;
        __syncthreads();
        s[threadIdx.x] += t;
        __syncthreads();
    }
    if (i < NN) g_off[i] = s[threadIdx.x] - v;   // exclusive within block
    if (threadIdx.x == SCAN_BS - 1) g_bsum[blockIdx.x] = s[SCAN_BS - 1];
}

__global__ __launch_bounds__(128) void scan2_kernel() {
    __shared__ int s[128];
    int tid = threadIdx.x;
    int v = (tid < NB) ? g_bsum[tid] : 0;
    s[tid] = v;
    __syncthreads();
#pragma unroll
    for (int o = 1; o < 128; o <<= 1) {
        int t = (tid >= o) ? s[tid - o] : 0;
        __syncthreads();
        s[tid] += t;
        __syncthreads();
    }
    if (tid < NB) g_bsum[tid] = s[tid] - v;      // exclusive block offsets
}

__global__ __launch_bounds__(256) void scan3_kernel() {
    int i = blockIdx.x * 256 + threadIdx.x;
    if (i < NN) {
        int o = g_off[i] + g_bsum[i >> 10];
        g_off[i] = o;
        g_pos[i] = o;
    }
    if (i == 0) g_off[NN] = NE;
}

__global__ __launch_bounds__(256) void scatter_kernel(
    const int* __restrict__ er, const int* __restrict__ ec,
    const float* __restrict__ ev) {
    int i = blockIdx.x * 256 + threadIdx.x;
    if (i >= NE) return;
    int r = __ldg(er + i);
    int p = atomicAdd(&g_pos[r], 1);
    g_ecol[p] = __ldg(ec + i);
    g_eval[p] = __ldg(ev + i);
}

// ---------------------------------------------------------------------------
// GEMM: C[NN,64] = act(A)[NN,K] @ W[K,64] + bias ; act = ReLU if RELU
// 256 threads, 64x64 tile, 4x4 register blocking, k-vectorized LDS128.
// ---------------------------------------------------------------------------
template <int K, bool RELU>
__global__ __launch_bounds__(256) void gemm64_kernel(
    const float* __restrict__ A, const float* __restrict__ W,
    const float* __restrict__ bias, float* __restrict__ C) {
    __shared__ float As[64][68];   // [row][k], pad 68 keeps float4 k-loads aligned
    __shared__ float Ws[64][64];   // [k][col]

    const int t  = threadIdx.x;
    const int tx = t & 15;
    const int ty = t >> 4;
    const int row0 = blockIdx.x * 64;

    float acc[4][4];
#pragma unroll
    for (int i = 0; i < 4; i++)
#pragma unroll
        for (int j = 0; j < 4; j++) acc[i][j] = 0.f;

    const int lr = t >> 4;
    const int lk = (t & 15) << 2;

    for (int kt = 0; kt < K; kt += 64) {
#pragma unroll
        for (int i = 0; i < 4; i++) {
            int r = lr + i * 16;
            int grow = row0 + r;
            float4 v = make_float4(0.f, 0.f, 0.f, 0.f);
            if (grow < NN)
                v = *reinterpret_cast<const float4*>(A + (size_t)grow * K + kt + lk);
            if (RELU) {
                v.x = fmaxf(v.x, 0.f); v.y = fmaxf(v.y, 0.f);
                v.z = fmaxf(v.z, 0.f); v.w = fmaxf(v.w, 0.f);
            }
            *reinterpret_cast<float4*>(&As[r][lk]) = v;
        }
        {
            const float4* Wg = reinterpret_cast<const float4*>(W + (size_t)kt * 64);
            float4* Wsv = reinterpret_cast<float4*>(&Ws[0][0]);
#pragma unroll
            for (int i = 0; i < 4; i++) Wsv[t + i * 256] = Wg[t + i * 256];
        }
        __syncthreads();

#pragma unroll
        for (int kk = 0; kk < 64; kk += 4) {
            float4 a0 = *reinterpret_cast<const float4*>(&As[(ty << 2) + 0][kk]);
            float4 a1 = *reinterpret_cast<const float4*>(&As[(ty << 2) + 1][kk]);
            float4 a2 = *reinterpret_cast<const float4*>(&As[(ty << 2) + 2][kk]);
            float4 a3 = *reinterpret_cast<const float4*>(&As[(ty << 2) + 3][kk]);
#pragma unroll
            for (int j = 0; j < 4; j++) {
                float4 b = *reinterpret_cast<const float4*>(&Ws[kk + j][tx << 2]);
                float s0 = (j == 0) ? a0.x : (j == 1) ? a0.y : (j == 2) ? a0.z : a0.w;
                float s1 = (j == 0) ? a1.x : (j == 1) ? a1.y : (j == 2) ? a1.z : a1.w;
                float s2 = (j == 0) ? a2.x : (j == 1) ? a2.y : (j == 2) ? a2.z : a2.w;
                float s3 = (j == 0) ? a3.x : (j == 1) ? a3.y : (j == 2) ? a3.z : a3.w;
                acc[0][0] += s0 * b.x; acc[0][1] += s0 * b.y; acc[0][2] += s0 * b.z; acc[0][3] += s0 * b.w;
                acc[1][0] += s1 * b.x; acc[1][1] += s1 * b.y; acc[1][2] += s1 * b.z; acc[1][3] += s1 * b.w;
                acc[2][0] += s2 * b.x; acc[2][1] += s2 * b.y; acc[2][2] += s2 * b.z; acc[2][3] += s2 * b.w;
                acc[3][0] += s3 * b.x; acc[3][1] += s3 * b.y; acc[3][2] += s3 * b.z; acc[3][3] += s3 * b.w;
            }
        }
        __syncthreads();
    }

    float4 bv = *reinterpret_cast<const float4*>(bias + (tx << 2));
#pragma unroll
    for (int i = 0; i < 4; i++) {
        int grow = row0 + (ty << 2) + i;
        if (grow < NN) {
            float4 o = make_float4(acc[i][0] + bv.x, acc[i][1] + bv.y,
                                   acc[i][2] + bv.z, acc[i][3] + bv.w);
            *reinterpret_cast<float4*>(C + (size_t)grow * 64 + (tx << 2)) = o;
        }
    }
}

// ---------------------------------------------------------------------------
// CSR SpMM gather helper: 16 threads per row, register accumulate.
// ---------------------------------------------------------------------------
__device__ __forceinline__ float4 csr_row_acc(const float* __restrict__ dense,
                                              int row, int lane4) {
    int s = __ldg(g_off + row), e = __ldg(g_off + row + 1);
    float4 acc = make_float4(0.f, 0.f, 0.f, 0.f);
    int i = s;
    for (; i + 2 <= e; i += 2) {
        int c0 = __ldg(g_ecol + i);
        int c1 = __ldg(g_ecol + i + 1);
        float v0 = __ldg(g_eval + i);
        float v1 = __ldg(g_eval + i + 1);
        float4 d0 = *reinterpret_cast<const float4*>(dense + (size_t)c0 * HID + lane4);
        float4 d1 = *reinterpret_cast<const float4*>(dense + (size_t)c1 * HID + lane4);
        acc.x += v0 * d0.x + v1 * d1.x;
        acc.y += v0 * d0.y + v1 * d1.y;
        acc.z += v0 * d0.z + v1 * d1.z;
        acc.w += v0 * d0.w + v1 * d1.w;
    }
    if (i < e) {
        int c0 = __ldg(g_ecol + i);
        float v0 = __ldg(g_eval + i);
        float4 d0 = *reinterpret_cast<const float4*>(dense + (size_t)c0 * HID + lane4);
        acc.x += v0 * d0.x; acc.y += v0 * d0.y;
        acc.z += v0 * d0.z; acc.w += v0 * d0.w;
    }
    return acc;
}

__global__ __launch_bounds__(256) void spmm_csr_kernel(
    const float* __restrict__ dense, float* __restrict__ out) {
    int row = blockIdx.x * 16 + (threadIdx.x >> 4);
    if (row >= NN) return;
    int lane4 = (threadIdx.x & 15) << 2;
    float4 acc = csr_row_acc(dense, row, lane4);
    *reinterpret_cast<float4*>(out + (size_t)row * HID + lane4) = acc;
}

// ---------------------------------------------------------------------------
// Fused: h2 = spmm(dense) ; out = log_softmax(h2 @ Wc + bc)
// Phase A: 16 rows/block via CSR gather into smem. Phase B: warp-per-node.
// ---------------------------------------------------------------------------
__global__ __launch_bounds__(256) void spmm_cls_kernel(
    const float* __restrict__ dense, const float* __restrict__ Wc,
    const float* __restrict__ bc, float* __restrict__ out) {
    __shared__ float hs[16][68];
    __shared__ float Wcs[HID * NC];
    __shared__ float bcs[NC];

    const int t = threadIdx.x;
    for (int i = t; i < HID * NC; i += 256) Wcs[i] = Wc[i];
    if (t < NC) bcs[t] = bc[t];

    const int lrow = t >> 4;
    const int row = blockIdx.x * 16 + lrow;
    const int lane4 = (t & 15) << 2;

    float4 acc = make_float4(0.f, 0.f, 0.f, 0.f);
    if (row < NN) acc = csr_row_acc(dense, row, lane4);
    *reinterpret_cast<float4*>(&hs[lrow][lane4]) = acc;
    __syncthreads();

    const int w = t >> 5, lane = t & 31;
    const int j2 = lane + 32;
    const int j2c = (j2 < NC) ? j2 : 0;

    for (int rr = w; rr < 16; rr += 8) {
        int node = blockIdx.x * 16 + rr;
        if (node >= NN) continue;

        float l1 = bcs[lane];
        float l2 = bcs[j2c];
#pragma unroll 8
        for (int k = 0; k < HID; k++) {
            float h = hs[rr][k];
            l1 += h * Wcs[k * NC + lane];
            l2 += h * Wcs[k * NC + j2c];
        }
        if (j2 >= NC) l2 = -INFINITY;

        float m = fmaxf(l1, l2);
#pragma unroll
        for (int o = 16; o; o >>= 1) m = fmaxf(m, __shfl_xor_sync(0xffffffffu, m, o));
        float s = expf(l1 - m) + ((j2 < NC) ? expf(l2 - m) : 0.f);
#pragma unroll
        for (int o = 16; o; o >>= 1) s += __shfl_xor_sync(0xffffffffu, s, o);
        float lse = m + logf(s);

        out[(size_t)node * NC + lane] = l1 - lse;
        if (j2 < NC) out[(size_t)node * NC + j2] = l2 - lse;
    }
}

// ---------------------------------------------------------------------------
extern "C" void kernel_launch(void* const* d_in, const int* in_sizes, int n_in,
                              void* d_out, int out_size) {
    const float* x  = (const float*)d_in[0];
    const int*   er = (const int*)d_in[1];
    const int*   ec = (const int*)d_in[2];
    const float* ev = (const float*)d_in[3];
    const float* W1 = (const float*)d_in[4];
    const float* b1 = (const float*)d_in[5];
    const float* W2 = (const float*)d_in[6];
    const float* b2 = (const float*)d_in[7];
    const float* Wc = (const float*)d_in[8];
    const float* bc = (const float*)d_in[9];
    float* out = (float*)d_out;

    float *bufA, *bufB;
    cudaGetSymbolAddress((void**)&bufA, g_bufA);
    cudaGetSymbolAddress((void**)&bufB, g_bufB);

    const int node_grid = (NN + 255) / 256;          // 391
    const int edge_grid = (NE + 255) / 256;          // 6250
    const int gemm_grid = (NN + 63) / 64;            // 1563
    const int spmm_grid = (NN + 15) / 16;            // 6250

    // --- CSR build (reused by both SpMMs) ---
    zero_deg_kernel<<<node_grid, 256>>>();
    hist_kernel<<<edge_grid, 256>>>(er);
    scan1_kernel<<<NB, SCAN_BS>>>();
    scan2_kernel<<<1, 128>>>();
    scan3_kernel<<<node_grid, 256>>>();
    scatter_kernel<<<edge_grid, 256>>>(er, ec, ev);

    // --- Layer 1: support = x@W1+b1 ; h1 = spmm(support) (relu deferred) ---
    gemm64_kernel<IND, false><<<gemm_grid, 256>>>(x, W1, b1, bufA);
    spmm_csr_kernel<<<spmm_grid, 256>>>(bufA, bufB);

    // --- Layer 2: support = relu(h1)@W2+b2 ; out = cls(spmm(support)) ---
    gemm64_kernel<HID, true><<<gemm_grid, 256>>>(bufB, W2, b2, bufA);
    spmm_cls_kernel<<<spmm_grid, 256>>>(bufA, Wc, bc, out);
}

// round 7
// speedup vs baseline: 1.3062x; 1.0012x over previous
#include <cuda_runtime.h>
#include <math.h>

#define NN 100000
#define NE 1600000
#define IND 128
#define HID 64
#define NC 40
#define SCAN_BS 1024
#define NB 98              // ceil(NN/1024)

// Scratch (allocation-free per harness rules)
__device__ float g_bufA[(size_t)NN * HID];
__device__ float g_bufB[(size_t)NN * HID];
__device__ int   g_off[NN + 1];
__device__ int   g_pos[NN];
__device__ int   g_bsum[NB];
__device__ int   g_ecol[NE];
__device__ float g_eval[NE];

// ---------------------------------------------------------------------------
// CSR build
// ---------------------------------------------------------------------------
__global__ __launch_bounds__(256) void hist_kernel(const int* __restrict__ er) {
    int i = blockIdx.x * 256 + threadIdx.x;
    if (i < NE) atomicAdd(&g_off[__ldg(er + i)], 1);
}

__global__ __launch_bounds__(SCAN_BS) void scan1_kernel() {
    __shared__ int s[SCAN_BS];
    int i = blockIdx.x * SCAN_BS + threadIdx.x;
    int v = (i < NN) ? g_off[i] : 0;
    s[threadIdx.x] = v;
    __syncthreads();
#pragma unroll
    for (int o = 1; o < SCAN_BS; o <<= 1) {
        int t = (threadIdx.x >= o) ? s[threadIdx.x - o] : 0;
        __syncthreads();
        s[threadIdx.x] += t;
        __syncthreads();
    }
    if (i < NN) g_off[i] = s[threadIdx.x] - v;   // exclusive within block
    if (threadIdx.x == SCAN_BS - 1) g_bsum[blockIdx.x] = s[SCAN_BS - 1];
}

// Fused: each block redundantly scans the 98 block sums in smem, then applies.
__global__ __launch_bounds__(256) void scan3_kernel() {
    __shared__ int s[128];
    const int tid = threadIdx.x;
    int v = 0;
    if (tid < 128) {
        v = (tid < NB) ? g_bsum[tid] : 0;
        s[tid] = v;
    }
    __syncthreads();
#pragma unroll
    for (int o = 1; o < 128; o <<= 1) {
        int t = (tid < 128 && tid >= o) ? s[tid - o] : 0;
        __syncthreads();
        if (tid < 128) s[tid] += t;
        __syncthreads();
    }
    if (tid < 128) s[tid] -= v;   // exclusive block offsets
    __syncthreads();

    int i = blockIdx.x * 256 + tid;
    if (i < NN) {
        int o = g_off[i] + s[i >> 10];
        g_off[i] = o;
        g_pos[i] = o;
    }
    if (i == 0) g_off[NN] = NE;
}

__global__ __launch_bounds__(256) void scatter_kernel(
    const int* __restrict__ er, const int* __restrict__ ec,
    const float* __restrict__ ev) {
    int i = blockIdx.x * 256 + threadIdx.x;
    if (i >= NE) return;
    int r = __ldg(er + i);
    int p = atomicAdd(&g_pos[r], 1);
    g_ecol[p] = __ldg(ec + i);
    g_eval[p] = __ldg(ev + i);
}

// ---------------------------------------------------------------------------
// GEMM: C[NN,64] = act(A)[NN,K] @ W[K,64] + bias ; act = ReLU if RELU
// 256 threads, 128x64 tile, 8x4 register blocking, k-tile 32.
// 12 LDS128 per 128 FMA -> fma-pipe bound.
// ---------------------------------------------------------------------------
template <int K, bool RELU>
__global__ __launch_bounds__(256) void gemm128_kernel(
    const float* __restrict__ A, const float* __restrict__ W,
    const float* __restrict__ bias, float* __restrict__ C) {
    __shared__ float As[128][36];  // [row][k], pad 36 keeps float4 alignment
    __shared__ float Ws[32][64];   // [k][col]

    const int t  = threadIdx.x;
    const int tx = t & 15;         // col group (4 cols)
    const int ty = t >> 4;         // row group (8 rows)
    const int row0 = blockIdx.x * 128;

    float acc[8][4];
#pragma unroll
    for (int i = 0; i < 8; i++)
#pragma unroll
        for (int j = 0; j < 4; j++) acc[i][j] = 0.f;

    for (int kt = 0; kt < K; kt += 32) {
        // A tile: 128 rows x 32 k = 1024 float4, 4 per thread
#pragma unroll
        for (int u = 0; u < 4; u++) {
            int f = t + u * 256;
            int r = f >> 3;
            int kc = (f & 7) << 2;
            int grow = row0 + r;
            float4 v = make_float4(0.f, 0.f, 0.f, 0.f);
            if (grow < NN)
                v = *reinterpret_cast<const float4*>(A + (size_t)grow * K + kt + kc);
            if (RELU) {
                v.x = fmaxf(v.x, 0.f); v.y = fmaxf(v.y, 0.f);
                v.z = fmaxf(v.z, 0.f); v.w = fmaxf(v.w, 0.f);
            }
            *reinterpret_cast<float4*>(&As[r][kc]) = v;
        }
        // W tile: 32 k x 64 cols = 512 float4, 2 per thread
#pragma unroll
        for (int u = 0; u < 2; u++) {
            int f = t + u * 256;
            int r = f >> 4;
            int c = (f & 15) << 2;
            *reinterpret_cast<float4*>(&Ws[r][c]) =
                *reinterpret_cast<const float4*>(W + (size_t)(kt + r) * 64 + c);
        }
        __syncthreads();

#pragma unroll
        for (int kk = 0; kk < 32; kk += 4) {
            float4 a[8];
#pragma unroll
            for (int i = 0; i < 8; i++)
                a[i] = *reinterpret_cast<const float4*>(&As[(ty << 3) + i][kk]);
#pragma unroll
            for (int j = 0; j < 4; j++) {
                float4 b = *reinterpret_cast<const float4*>(&Ws[kk + j][tx << 2]);
#pragma unroll
                for (int i = 0; i < 8; i++) {
                    float s = (j == 0) ? a[i].x : (j == 1) ? a[i].y
                            : (j == 2) ? a[i].z : a[i].w;
                    acc[i][0] += s * b.x; acc[i][1] += s * b.y;
                    acc[i][2] += s * b.z; acc[i][3] += s * b.w;
                }
            }
        }
        __syncthreads();
    }

    float4 bv = *reinterpret_cast<const float4*>(bias + (tx << 2));
#pragma unroll
    for (int i = 0; i < 8; i++) {
        int grow = row0 + (ty << 3) + i;
        if (grow < NN) {
            float4 o = make_float4(acc[i][0] + bv.x, acc[i][1] + bv.y,
                                   acc[i][2] + bv.z, acc[i][3] + bv.w);
            *reinterpret_cast<float4*>(C + (size_t)grow * 64 + (tx << 2)) = o;
        }
    }
}

// ---------------------------------------------------------------------------
// CSR SpMM gather: 16 threads per row, unroll-4 for MLP.
// ---------------------------------------------------------------------------
__device__ __forceinline__ float4 csr_row_acc(const float* __restrict__ dense,
                                              int row, int lane4) {
    int s = __ldg(g_off + row), e = __ldg(g_off + row + 1);
    float4 acc = make_float4(0.f, 0.f, 0.f, 0.f);
    int i = s;
    for (; i + 4 <= e; i += 4) {
        int   c0 = __ldg(g_ecol + i),     c1 = __ldg(g_ecol + i + 1);
        int   c2 = __ldg(g_ecol + i + 2), c3 = __ldg(g_ecol + i + 3);
        float v0 = __ldg(g_eval + i),     v1 = __ldg(g_eval + i + 1);
        float v2 = __ldg(g_eval + i + 2), v3 = __ldg(g_eval + i + 3);
        float4 d0 = *reinterpret_cast<const float4*>(dense + (size_t)c0 * HID + lane4);
        float4 d1 = *reinterpret_cast<const float4*>(dense + (size_t)c1 * HID + lane4);
        float4 d2 = *reinterpret_cast<const float4*>(dense + (size_t)c2 * HID + lane4);
        float4 d3 = *reinterpret_cast<const float4*>(dense + (size_t)c3 * HID + lane4);
        acc.x += v0 * d0.x + v1 * d1.x + v2 * d2.x + v3 * d3.x;
        acc.y += v0 * d0.y + v1 * d1.y + v2 * d2.y + v3 * d3.y;
        acc.z += v0 * d0.z + v1 * d1.z + v2 * d2.z + v3 * d3.z;
        acc.w += v0 * d0.w + v1 * d1.w + v2 * d2.w + v3 * d3.w;
    }
    for (; i < e; i++) {
        int c0 = __ldg(g_ecol + i);
        float v0 = __ldg(g_eval + i);
        float4 d0 = *reinterpret_cast<const float4*>(dense + (size_t)c0 * HID + lane4);
        acc.x += v0 * d0.x; acc.y += v0 * d0.y;
        acc.z += v0 * d0.z; acc.w += v0 * d0.w;
    }
    return acc;
}

__global__ __launch_bounds__(256) void spmm_csr_kernel(
    const float* __restrict__ dense, float* __restrict__ out) {
    int row = blockIdx.x * 16 + (threadIdx.x >> 4);
    if (row >= NN) return;
    int lane4 = (threadIdx.x & 15) << 2;
    float4 acc = csr_row_acc(dense, row, lane4);
    *reinterpret_cast<float4*>(out + (size_t)row * HID + lane4) = acc;
}

// ---------------------------------------------------------------------------
// Fused: h2 = spmm(dense) ; out = log_softmax(h2 @ Wc + bc)
// ---------------------------------------------------------------------------
__global__ __launch_bounds__(256) void spmm_cls_kernel(
    const float* __restrict__ dense, const float* __restrict__ Wc,
    const float* __restrict__ bc, float* __restrict__ out) {
    __shared__ float hs[16][68];
    __shared__ float Wcs[HID * NC];
    __shared__ float bcs[NC];

    const int t = threadIdx.x;
    for (int i = t; i < HID * NC; i += 256) Wcs[i] = Wc[i];
    if (t < NC) bcs[t] = bc[t];

    const int lrow = t >> 4;
    const int row = blockIdx.x * 16 + lrow;
    const int lane4 = (t & 15) << 2;

    float4 acc = make_float4(0.f, 0.f, 0.f, 0.f);
    if (row < NN) acc = csr_row_acc(dense, row, lane4);
    *reinterpret_cast<float4*>(&hs[lrow][lane4]) = acc;
    __syncthreads();

    const int w = t >> 5, lane = t & 31;
    const int j2 = lane + 32;
    const int j2c = (j2 < NC) ? j2 : 0;

    for (int rr = w; rr < 16; rr += 8) {
        int node = blockIdx.x * 16 + rr;
        if (node >= NN) continue;

        float l1 = bcs[lane];
        float l2 = bcs[j2c];
#pragma unroll 8
        for (int k = 0; k < HID; k++) {
            float h = hs[rr][k];
            l1 += h * Wcs[k * NC + lane];
            l2 += h * Wcs[k * NC + j2c];
        }
        if (j2 >= NC) l2 = -INFINITY;

        float m = fmaxf(l1, l2);
#pragma unroll
        for (int o = 16; o; o >>= 1) m = fmaxf(m, __shfl_xor_sync(0xffffffffu, m, o));
        float s = expf(l1 - m) + ((j2 < NC) ? expf(l2 - m) : 0.f);
#pragma unroll
        for (int o = 16; o; o >>= 1) s += __shfl_xor_sync(0xffffffffu, s, o);
        float lse = m + logf(s);

        out[(size_t)node * NC + lane] = l1 - lse;
        if (j2 < NC) out[(size_t)node * NC + j2] = l2 - lse;
    }
}

// ---------------------------------------------------------------------------
extern "C" void kernel_launch(void* const* d_in, const int* in_sizes, int n_in,
                              void* d_out, int out_size) {
    const float* x  = (const float*)d_in[0];
    const int*   er = (const int*)d_in[1];
    const int*   ec = (const int*)d_in[2];
    const float* ev = (const float*)d_in[3];
    const float* W1 = (const float*)d_in[4];
    const float* b1 = (const float*)d_in[5];
    const float* W2 = (const float*)d_in[6];
    const float* b2 = (const float*)d_in[7];
    const float* Wc = (const float*)d_in[8];
    const float* bc = (const float*)d_in[9];
    float* out = (float*)d_out;

    float *bufA, *bufB;
    cudaGetSymbolAddress((void**)&bufA, g_bufA);
    cudaGetSymbolAddress((void**)&bufB, g_bufB);
    int* offp;
    cudaGetSymbolAddress((void**)&offp, g_off);

    const int node_grid = (NN + 255) / 256;          // 391
    const int edge_grid = (NE + 255) / 256;          // 6250
    const int gemm_grid = (NN + 127) / 128;          // 782
    const int spmm_grid = (NN + 15) / 16;            // 6250

    // --- CSR build (reused by both SpMMs) ---
    cudaMemsetAsync(offp, 0, (size_t)(NN + 1) * sizeof(int));
    hist_kernel<<<edge_grid, 256>>>(er);
    scan1_kernel<<<NB, SCAN_BS>>>();
    scan3_kernel<<<node_grid, 256>>>();
    scatter_kernel<<<edge_grid, 256>>>(er, ec, ev);

    // --- Layer 1: support = x@W1+b1 ; h1 = spmm(support) (relu deferred) ---
    gemm128_kernel<IND, false><<<gemm_grid, 256>>>(x, W1, b1, bufA);
    spmm_csr_kernel<<<spmm_grid, 256>>>(bufA, bufB);

    // --- Layer 2: support = relu(h1)@W2+b2 ; out = cls(spmm(support)) ---
    gemm128_kernel<HID, true><<<gemm_grid, 256>>>(bufB, W2, b2, bufA);
    spmm_cls_kernel<<<spmm_grid, 256>>>(bufA, Wc, bc, out);
}

// round 9
// speedup vs baseline: 1.3747x; 1.0524x over previous
#include <cuda_runtime.h>
#include <math.h>

#define NN 100000
#define NE 1600000
#define IND 128
#define HID 64
#define NC 40
#define SCAN_BS 1024
#define NB 98              // ceil(NN/1024)

// Scratch (allocation-free per harness rules)
__device__ float g_bufA[(size_t)NN * HID];
__device__ float g_bufB[(size_t)NN * HID];
__device__ int   g_off[NN + 1];
__device__ int   g_pos[NN];
__device__ int   g_bsum[NB];
__device__ int2  g_epack[NE];   // packed (col, val-bits)

// ---------------------------------------------------------------------------
// CSR build
// ---------------------------------------------------------------------------
__global__ __launch_bounds__(256) void hist_kernel(const int* __restrict__ er) {
    int i = blockIdx.x * 256 + threadIdx.x;
    if (i < NE) atomicAdd(&g_off[__ldg(er + i)], 1);
}

__global__ __launch_bounds__(SCAN_BS) void scan1_kernel() {
    __shared__ int s[SCAN_BS];
    int i = blockIdx.x * SCAN_BS + threadIdx.x;
    int v = (i < NN) ? g_off[i] : 0;
    s[threadIdx.x] = v;
    __syncthreads();
#pragma unroll
    for (int o = 1; o < SCAN_BS; o <<= 1) {
        int t = (threadIdx.x >= o) ? s[threadIdx.x - o] : 0;
        __syncthreads();
        s[threadIdx.x] += t;
        __syncthreads();
    }
    if (i < NN) g_off[i] = s[threadIdx.x] - v;   // exclusive within block
    if (threadIdx.x == SCAN_BS - 1) g_bsum[blockIdx.x] = s[SCAN_BS - 1];
}

// Fused: each block redundantly scans the 98 block sums in smem, then applies.
__global__ __launch_bounds__(256) void scan3_kernel() {
    __shared__ int s[128];
    const int tid = threadIdx.x;
    int v = 0;
    if (tid < 128) {
        v = (tid < NB) ? g_bsum[tid] : 0;
        s[tid] = v;
    }
    __syncthreads();
#pragma unroll
    for (int o = 1; o < 128; o <<= 1) {
        int t = (tid < 128 && tid >= o) ? s[tid - o] : 0;
        __syncthreads();
        if (tid < 128) s[tid] += t;
        __syncthreads();
    }
    if (tid < 128) s[tid] -= v;   // exclusive block offsets
    __syncthreads();

    int i = blockIdx.x * 256 + tid;
    if (i < NN) {
        int o = g_off[i] + s[i >> 10];
        g_off[i] = o;
        g_pos[i] = o;
    }
    if (i == 0) g_off[NN] = NE;
}

__global__ __launch_bounds__(256) void scatter_kernel(
    const int* __restrict__ er, const int* __restrict__ ec,
    const float* __restrict__ ev) {
    int i = blockIdx.x * 256 + threadIdx.x;
    if (i >= NE) return;
    int r = __ldg(er + i);
    int c = __ldg(ec + i);
    float v = __ldg(ev + i);
    int p = atomicAdd(&g_pos[r], 1);
    g_epack[p] = make_int2(c, __float_as_int(v));   // one 8B random store
}

// ---------------------------------------------------------------------------
// GEMM: C[NN,64] = act(A)[NN,K] @ W[K,64] + bias ; act = ReLU if RELU
// 256 threads, 128x64 tile, 8x4 register blocking, k-tile 32.
// ---------------------------------------------------------------------------
template <int K, bool RELU>
__global__ __launch_bounds__(256) void gemm128_kernel(
    const float* __restrict__ A, const float* __restrict__ W,
    const float* __restrict__ bias, float* __restrict__ C) {
    __shared__ float As[128][36];  // [row][k], pad 36 keeps float4 alignment
    __shared__ float Ws[32][64];   // [k][col]

    const int t  = threadIdx.x;
    const int tx = t & 15;         // col group (4 cols)
    const int ty = t >> 4;         // row group (8 rows)
    const int row0 = blockIdx.x * 128;

    float acc[8][4];
#pragma unroll
    for (int i = 0; i < 8; i++)
#pragma unroll
        for (int j = 0; j < 4; j++) acc[i][j] = 0.f;

    for (int kt = 0; kt < K; kt += 32) {
#pragma unroll
        for (int u = 0; u < 4; u++) {
            int f = t + u * 256;
            int r = f >> 3;
            int kc = (f & 7) << 2;
            int grow = row0 + r;
            float4 v = make_float4(0.f, 0.f, 0.f, 0.f);
            if (grow < NN)
                v = *reinterpret_cast<const float4*>(A + (size_t)grow * K + kt + kc);
            if (RELU) {
                v.x = fmaxf(v.x, 0.f); v.y = fmaxf(v.y, 0.f);
                v.z = fmaxf(v.z, 0.f); v.w = fmaxf(v.w, 0.f);
            }
            *reinterpret_cast<float4*>(&As[r][kc]) = v;
        }
#pragma unroll
        for (int u = 0; u < 2; u++) {
            int f = t + u * 256;
            int r = f >> 4;
            int c = (f & 15) << 2;
            *reinterpret_cast<float4*>(&Ws[r][c]) =
                *reinterpret_cast<const float4*>(W + (size_t)(kt + r) * 64 + c);
        }
        __syncthreads();

#pragma unroll
        for (int kk = 0; kk < 32; kk += 4) {
            float4 a[8];
#pragma unroll
            for (int i = 0; i < 8; i++)
                a[i] = *reinterpret_cast<const float4*>(&As[(ty << 3) + i][kk]);
#pragma unroll
            for (int j = 0; j < 4; j++) {
                float4 b = *reinterpret_cast<const float4*>(&Ws[kk + j][tx << 2]);
#pragma unroll
                for (int i = 0; i < 8; i++) {
                    float s = (j == 0) ? a[i].x : (j == 1) ? a[i].y
                            : (j == 2) ? a[i].z : a[i].w;
                    acc[i][0] += s * b.x; acc[i][1] += s * b.y;
                    acc[i][2] += s * b.z; acc[i][3] += s * b.w;
                }
            }
        }
        __syncthreads();
    }

    float4 bv = *reinterpret_cast<const float4*>(bias + (tx << 2));
#pragma unroll
    for (int i = 0; i < 8; i++) {
        int grow = row0 + (ty << 3) + i;
        if (grow < NN) {
            float4 o = make_float4(acc[i][0] + bv.x, acc[i][1] + bv.y,
                                   acc[i][2] + bv.z, acc[i][3] + bv.w);
            *reinterpret_cast<float4*>(C + (size_t)grow * 64 + (tx << 2)) = o;
        }
    }
}

// ---------------------------------------------------------------------------
// CSR SpMM gather: 16 threads per row, packed 8B edge loads, unroll-4.
// ---------------------------------------------------------------------------
__device__ __forceinline__ float4 csr_row_acc(const float* __restrict__ dense,
                                              int row, int lane4) {
    int s = __ldg(g_off + row), e = __ldg(g_off + row + 1);
    float4 acc = make_float4(0.f, 0.f, 0.f, 0.f);
    int i = s;
    for (; i + 4 <= e; i += 4) {
        int2 e0 = __ldg(g_epack + i);
        int2 e1 = __ldg(g_epack + i + 1);
        int2 e2 = __ldg(g_epack + i + 2);
        int2 e3 = __ldg(g_epack + i + 3);
        float v0 = __int_as_float(e0.y), v1 = __int_as_float(e1.y);
        float v2 = __int_as_float(e2.y), v3 = __int_as_float(e3.y);
        float4 d0 = *reinterpret_cast<const float4*>(dense + (size_t)e0.x * HID + lane4);
        float4 d1 = *reinterpret_cast<const float4*>(dense + (size_t)e1.x * HID + lane4);
        float4 d2 = *reinterpret_cast<const float4*>(dense + (size_t)e2.x * HID + lane4);
        float4 d3 = *reinterpret_cast<const float4*>(dense + (size_t)e3.x * HID + lane4);
        acc.x += v0 * d0.x + v1 * d1.x + v2 * d2.x + v3 * d3.x;
        acc.y += v0 * d0.y + v1 * d1.y + v2 * d2.y + v3 * d3.y;
        acc.z += v0 * d0.z + v1 * d1.z + v2 * d2.z + v3 * d3.z;
        acc.w += v0 * d0.w + v1 * d1.w + v2 * d2.w + v3 * d3.w;
    }
    for (; i < e; i++) {
        int2 e0 = __ldg(g_epack + i);
        float v0 = __int_as_float(e0.y);
        float4 d0 = *reinterpret_cast<const float4*>(dense + (size_t)e0.x * HID + lane4);
        acc.x += v0 * d0.x; acc.y += v0 * d0.y;
        acc.z += v0 * d0.z; acc.w += v0 * d0.w;
    }
    return acc;
}

__global__ __launch_bounds__(256) void spmm_csr_kernel(
    const float* __restrict__ dense, float* __restrict__ out) {
    int row = blockIdx.x * 16 + (threadIdx.x >> 4);
    if (row >= NN) return;
    int lane4 = (threadIdx.x & 15) << 2;
    float4 acc = csr_row_acc(dense, row, lane4);
    *reinterpret_cast<float4*>(out + (size_t)row * HID + lane4) = acc;
}

// ---------------------------------------------------------------------------
// Fused: h2 = spmm(dense) ; out = log_softmax(h2 @ Wc + bc)
// ---------------------------------------------------------------------------
__global__ __launch_bounds__(256) void spmm_cls_kernel(
    const float* __restrict__ dense, const float* __restrict__ Wc,
    const float* __restrict__ bc, float* __restrict__ out) {
    __shared__ float hs[16][68];
    __shared__ float Wcs[HID * NC];
    __shared__ float bcs[NC];

    const int t = threadIdx.x;
    for (int i = t; i < HID * NC; i += 256) Wcs[i] = Wc[i];
    if (t < NC) bcs[t] = bc[t];

    const int lrow = t >> 4;
    const int row = blockIdx.x * 16 + lrow;
    const int lane4 = (t & 15) << 2;

    float4 acc = make_float4(0.f, 0.f, 0.f, 0.f);
    if (row < NN) acc = csr_row_acc(dense, row, lane4);
    *reinterpret_cast<float4*>(&hs[lrow][lane4]) = acc;
    __syncthreads();

    const int w = t >> 5, lane = t & 31;
    const int j2 = lane + 32;
    const int j2c = (j2 < NC) ? j2 : 0;

    for (int rr = w; rr < 16; rr += 8) {
        int node = blockIdx.x * 16 + rr;
        if (node >= NN) continue;

        float l1 = bcs[lane];
        float l2 = bcs[j2c];
#pragma unroll 8
        for (int k = 0; k < HID; k++) {
            float h = hs[rr][k];
            l1 += h * Wcs[k * NC + lane];
            l2 += h * Wcs[k * NC + j2c];
        }
        if (j2 >= NC) l2 = -INFINITY;

        float m = fmaxf(l1, l2);
#pragma unroll
        for (int o = 16; o; o >>= 1) m = fmaxf(m, __shfl_xor_sync(0xffffffffu, m, o));
        float s = expf(l1 - m) + ((j2 < NC) ? expf(l2 - m) : 0.f);
#pragma unroll
        for (int o = 16; o; o >>= 1) s += __shfl_xor_sync(0xffffffffu, s, o);
        float lse = m + logf(s);

        out[(size_t)node * NC + lane] = l1 - lse;
        if (j2 < NC) out[(size_t)node * NC + j2] = l2 - lse;
    }
}

// ---------------------------------------------------------------------------
extern "C" void kernel_launch(void* const* d_in, const int* in_sizes, int n_in,
                              void* d_out, int out_size) {
    const float* x  = (const float*)d_in[0];
    const int*   er = (const int*)d_in[1];
    const int*   ec = (const int*)d_in[2];
    const float* ev = (const float*)d_in[3];
    const float* W1 = (const float*)d_in[4];
    const float* b1 = (const float*)d_in[5];
    const float* W2 = (const float*)d_in[6];
    const float* b2 = (const float*)d_in[7];
    const float* Wc = (const float*)d_in[8];
    const float* bc = (const float*)d_in[9];
    float* out = (float*)d_out;

    float *bufA, *bufB;
    cudaGetSymbolAddress((void**)&bufA, g_bufA);
    cudaGetSymbolAddress((void**)&bufB, g_bufB);
    int* offp;
    cudaGetSymbolAddress((void**)&offp, g_off);

    // One-time resource init (streams/events only; identical GPU work each call).
    static cudaStream_t sB = nullptr;
    static cudaEvent_t evFork = nullptr, evJoin = nullptr;
    if (sB == nullptr) {
        cudaStreamCreateWithFlags(&sB, cudaStreamNonBlocking);
        cudaEventCreateWithFlags(&evFork, cudaEventDisableTiming);
        cudaEventCreateWithFlags(&evJoin, cudaEventDisableTiming);
    }

    const int node_grid = (NN + 255) / 256;          // 391
    const int edge_grid = (NE + 255) / 256;          // 6250
    const int gemm_grid = (NN + 127) / 128;          // 782
    const int spmm_grid = (NN + 15) / 16;            // 6250

    // --- Fork: CSR build on side stream, gemm1 on capture stream ---
    cudaEventRecord(evFork, 0);
    cudaStreamWaitEvent(sB, evFork, 0);

    cudaMemsetAsync(offp, 0, (size_t)(NN + 1) * sizeof(int), sB);
    hist_kernel<<<edge_grid, 256, 0, sB>>>(er);
    scan1_kernel<<<NB, SCAN_BS, 0, sB>>>();
    scan3_kernel<<<node_grid, 256, 0, sB>>>();
    scatter_kernel<<<edge_grid, 256, 0, sB>>>(er, ec, ev);
    cudaEventRecord(evJoin, sB);

    // Layer 1 GEMM overlaps the build: support = x@W1+b1
    gemm128_kernel<IND, false><<<gemm_grid, 256>>>(x, W1, b1, bufA);

    // --- Join: spmm1 needs both CSR and support ---
    cudaStreamWaitEvent(0, evJoin, 0);
    spmm_csr_kernel<<<spmm_grid, 256>>>(bufA, bufB);

    // --- Layer 2: support = relu(h1)@W2+b2 ; out = cls(spmm(support)) ---
    gemm128_kernel<HID, true><<<gemm_grid, 256>>>(bufB, W2, b2, bufA);
    spmm_cls_kernel<<<spmm_grid, 256>>>(bufA, Wc, bc, out);
}

// round 10
// speedup vs baseline: 1.4844x; 1.0798x over previous
#include <cuda_runtime.h>
#include <cuda_fp16.h>
#include <math.h>

#define NN 100000
#define NE 1600000
#define IND 128
#define HID 64
#define NC 40
#define SCAN_BS 1024
#define NB 98              // ceil(NN/1024)

// Scratch (allocation-free per harness rules)
__device__ __half g_hA[(size_t)NN * HID];   // half intermediates (12.8 MB each)
__device__ __half g_hB[(size_t)NN * HID];
__device__ int    g_off[NN + 1];
__device__ int    g_pos[NN];
__device__ int    g_bsum[NB];
__device__ int2   g_epack[NE];              // packed (col, val-bits)

// ---------------------------------------------------------------------------
// CSR build
// ---------------------------------------------------------------------------
__global__ __launch_bounds__(256) void hist_kernel(const int4* __restrict__ er4) {
    int i = blockIdx.x * 256 + threadIdx.x;
    if (i >= NE / 4) return;
    int4 r = __ldg(er4 + i);
    atomicAdd(&g_off[r.x], 1);
    atomicAdd(&g_off[r.y], 1);
    atomicAdd(&g_off[r.z], 1);
    atomicAdd(&g_off[r.w], 1);
}

__global__ __launch_bounds__(SCAN_BS) void scan1_kernel() {
    __shared__ int s[SCAN_BS];
    int i = blockIdx.x * SCAN_BS + threadIdx.x;
    int v = (i < NN) ? g_off[i] : 0;
    s[threadIdx.x] = v;
    __syncthreads();
#pragma unroll
    for (int o = 1; o < SCAN_BS; o <<= 1) {
        int t = (threadIdx.x >= o) ? s[threadIdx.x - o] : 0;
        __syncthreads();
        s[threadIdx.x] += t;
        __syncthreads();
    }
    if (i < NN) g_off[i] = s[threadIdx.x] - v;   // exclusive within block
    if (threadIdx.x == SCAN_BS - 1) g_bsum[blockIdx.x] = s[SCAN_BS - 1];
}

// Fused: each block redundantly scans the 98 block sums in smem, then applies.
__global__ __launch_bounds__(256) void scan3_kernel() {
    __shared__ int s[128];
    const int tid = threadIdx.x;
    int v = 0;
    if (tid < 128) {
        v = (tid < NB) ? g_bsum[tid] : 0;
        s[tid] = v;
    }
    __syncthreads();
#pragma unroll
    for (int o = 1; o < 128; o <<= 1) {
        int t = (tid < 128 && tid >= o) ? s[tid - o] : 0;
        __syncthreads();
        if (tid < 128) s[tid] += t;
        __syncthreads();
    }
    if (tid < 128) s[tid] -= v;   // exclusive block offsets
    __syncthreads();

    int i = blockIdx.x * 256 + tid;
    if (i < NN) {
        int o = g_off[i] + s[i >> 10];
        g_off[i] = o;
        g_pos[i] = o;
    }
    if (i == 0) g_off[NN] = NE;
}

// ILP-4 scatter: 4 independent atomic->store chains per thread.
__global__ __launch_bounds__(256) void scatter_kernel(
    const int4* __restrict__ er4, const int4* __restrict__ ec4,
    const float4* __restrict__ ev4) {
    int i = blockIdx.x * 256 + threadIdx.x;
    if (i >= NE / 4) return;
    int4 r = __ldg(er4 + i);
    int4 c = __ldg(ec4 + i);
    float4 v = __ldg(ev4 + i);
    int p0 = atomicAdd(&g_pos[r.x], 1);
    int p1 = atomicAdd(&g_pos[r.y], 1);
    int p2 = atomicAdd(&g_pos[r.z], 1);
    int p3 = atomicAdd(&g_pos[r.w], 1);
    g_epack[p0] = make_int2(c.x, __float_as_int(v.x));
    g_epack[p1] = make_int2(c.y, __float_as_int(v.y));
    g_epack[p2] = make_int2(c.z, __float_as_int(v.z));
    g_epack[p3] = make_int2(c.w, __float_as_int(v.w));
}

// ---------------------------------------------------------------------------
// GEMM: C[NN,64](half) = act(A)[NN,K] @ W[K,64] + bias
// HIN: A is half (converted+ReLU on load). fp32 compute, half store.
// ---------------------------------------------------------------------------
template <int K, bool RELU, bool HIN>
__global__ __launch_bounds__(256) void gemm128_kernel(
    const void* __restrict__ Av, const float* __restrict__ W,
    const float* __restrict__ bias, __half* __restrict__ C) {
    __shared__ float As[128][36];
    __shared__ float Ws[32][64];

    const int t  = threadIdx.x;
    const int tx = t & 15;
    const int ty = t >> 4;
    const int row0 = blockIdx.x * 128;

    float acc[8][4];
#pragma unroll
    for (int i = 0; i < 8; i++)
#pragma unroll
        for (int j = 0; j < 4; j++) acc[i][j] = 0.f;

    for (int kt = 0; kt < K; kt += 32) {
#pragma unroll
        for (int u = 0; u < 4; u++) {
            int f = t + u * 256;
            int r = f >> 3;
            int kc = (f & 7) << 2;
            int grow = row0 + r;
            float4 v = make_float4(0.f, 0.f, 0.f, 0.f);
            if (grow < NN) {
                if (HIN) {
                    const __half* A = (const __half*)Av;
                    uint2 raw = __ldg(reinterpret_cast<const uint2*>(
                        A + (size_t)grow * K + kt + kc));
                    __half2 h0 = *reinterpret_cast<__half2*>(&raw.x);
                    __half2 h1 = *reinterpret_cast<__half2*>(&raw.y);
                    float2 f0 = __half22float2(h0);
                    float2 f1 = __half22float2(h1);
                    v = make_float4(f0.x, f0.y, f1.x, f1.y);
                } else {
                    const float* A = (const float*)Av;
                    v = *reinterpret_cast<const float4*>(A + (size_t)grow * K + kt + kc);
                }
            }
            if (RELU) {
                v.x = fmaxf(v.x, 0.f); v.y = fmaxf(v.y, 0.f);
                v.z = fmaxf(v.z, 0.f); v.w = fmaxf(v.w, 0.f);
            }
            *reinterpret_cast<float4*>(&As[r][kc]) = v;
        }
#pragma unroll
        for (int u = 0; u < 2; u++) {
            int f = t + u * 256;
            int r = f >> 4;
            int c = (f & 15) << 2;
            *reinterpret_cast<float4*>(&Ws[r][c]) =
                *reinterpret_cast<const float4*>(W + (size_t)(kt + r) * 64 + c);
        }
        __syncthreads();

#pragma unroll
        for (int kk = 0; kk < 32; kk += 4) {
            float4 a[8];
#pragma unroll
            for (int i = 0; i < 8; i++)
                a[i] = *reinterpret_cast<const float4*>(&As[(ty << 3) + i][kk]);
#pragma unroll
            for (int j = 0; j < 4; j++) {
                float4 b = *reinterpret_cast<const float4*>(&Ws[kk + j][tx << 2]);
#pragma unroll
                for (int i = 0; i < 8; i++) {
                    float s = (j == 0) ? a[i].x : (j == 1) ? a[i].y
                            : (j == 2) ? a[i].z : a[i].w;
                    acc[i][0] += s * b.x; acc[i][1] += s * b.y;
                    acc[i][2] += s * b.z; acc[i][3] += s * b.w;
                }
            }
        }
        __syncthreads();
    }

    float4 bv = *reinterpret_cast<const float4*>(bias + (tx << 2));
#pragma unroll
    for (int i = 0; i < 8; i++) {
        int grow = row0 + (ty << 3) + i;
        if (grow < NN) {
            __half2 o01 = __floats2half2_rn(acc[i][0] + bv.x, acc[i][1] + bv.y);
            __half2 o23 = __floats2half2_rn(acc[i][2] + bv.z, acc[i][3] + bv.w);
            uint2 st;
            st.x = *reinterpret_cast<unsigned*>(&o01);
            st.y = *reinterpret_cast<unsigned*>(&o23);
            *reinterpret_cast<uint2*>(C + (size_t)grow * 64 + (tx << 2)) = st;
        }
    }
}

// ---------------------------------------------------------------------------
// CSR SpMM gather (half dense, fp32 acc): 16 threads/row, 8B loads, unroll-4.
// ---------------------------------------------------------------------------
__device__ __forceinline__ float4 csr_row_acc_h(const __half* __restrict__ dense,
                                                int row, int lane) {
    int s = __ldg(g_off + row), e = __ldg(g_off + row + 1);
    const __half* base = dense + lane * 4;
    float4 acc = make_float4(0.f, 0.f, 0.f, 0.f);
    int i = s;
    for (; i + 4 <= e; i += 4) {
        int2 e0 = __ldg(g_epack + i);
        int2 e1 = __ldg(g_epack + i + 1);
        int2 e2 = __ldg(g_epack + i + 2);
        int2 e3 = __ldg(g_epack + i + 3);
        uint2 r0 = __ldg(reinterpret_cast<const uint2*>(base + (size_t)e0.x * HID));
        uint2 r1 = __ldg(reinterpret_cast<const uint2*>(base + (size_t)e1.x * HID));
        uint2 r2 = __ldg(reinterpret_cast<const uint2*>(base + (size_t)e2.x * HID));
        uint2 r3 = __ldg(reinterpret_cast<const uint2*>(base + (size_t)e3.x * HID));
        float v0 = __int_as_float(e0.y), v1 = __int_as_float(e1.y);
        float v2 = __int_as_float(e2.y), v3 = __int_as_float(e3.y);
        float2 a0 = __half22float2(*reinterpret_cast<__half2*>(&r0.x));
        float2 b0 = __half22float2(*reinterpret_cast<__half2*>(&r0.y));
        float2 a1 = __half22float2(*reinterpret_cast<__half2*>(&r1.x));
        float2 b1 = __half22float2(*reinterpret_cast<__half2*>(&r1.y));
        float2 a2 = __half22float2(*reinterpret_cast<__half2*>(&r2.x));
        float2 b2 = __half22float2(*reinterpret_cast<__half2*>(&r2.y));
        float2 a3 = __half22float2(*reinterpret_cast<__half2*>(&r3.x));
        float2 b3 = __half22float2(*reinterpret_cast<__half2*>(&r3.y));
        acc.x += v0 * a0.x + v1 * a1.x + v2 * a2.x + v3 * a3.x;
        acc.y += v0 * a0.y + v1 * a1.y + v2 * a2.y + v3 * a3.y;
        acc.z += v0 * b0.x + v1 * b1.x + v2 * b2.x + v3 * b3.x;
        acc.w += v0 * b0.y + v1 * b1.y + v2 * b2.y + v3 * b3.y;
    }
    for (; i < e; i++) {
        int2 e0 = __ldg(g_epack + i);
        float v0 = __int_as_float(e0.y);
        uint2 r0 = __ldg(reinterpret_cast<const uint2*>(base + (size_t)e0.x * HID));
        float2 a0 = __half22float2(*reinterpret_cast<__half2*>(&r0.x));
        float2 b0 = __half22float2(*reinterpret_cast<__half2*>(&r0.y));
        acc.x += v0 * a0.x; acc.y += v0 * a0.y;
        acc.z += v0 * b0.x; acc.w += v0 * b0.y;
    }
    return acc;
}

__global__ __launch_bounds__(256) void spmm_csr_kernel(
    const __half* __restrict__ dense, __half* __restrict__ out) {
    int row = blockIdx.x * 16 + (threadIdx.x >> 4);
    if (row >= NN) return;
    int lane = threadIdx.x & 15;
    float4 acc = csr_row_acc_h(dense, row, lane);
    __half2 o01 = __floats2half2_rn(acc.x, acc.y);
    __half2 o23 = __floats2half2_rn(acc.z, acc.w);
    uint2 st;
    st.x = *reinterpret_cast<unsigned*>(&o01);
    st.y = *reinterpret_cast<unsigned*>(&o23);
    *reinterpret_cast<uint2*>(out + (size_t)row * HID + lane * 4) = st;
}

// ---------------------------------------------------------------------------
// Fused: h2 = spmm(dense) ; out = log_softmax(h2 @ Wc + bc)  (fp32 math)
// ---------------------------------------------------------------------------
__global__ __launch_bounds__(256) void spmm_cls_kernel(
    const __half* __restrict__ dense, const float* __restrict__ Wc,
    const float* __restrict__ bc, float* __restrict__ out) {
    __shared__ float hs[16][68];
    __shared__ float Wcs[HID * NC];
    __shared__ float bcs[NC];

    const int t = threadIdx.x;
    for (int i = t; i < HID * NC; i += 256) Wcs[i] = Wc[i];
    if (t < NC) bcs[t] = bc[t];

    const int lrow = t >> 4;
    const int row = blockIdx.x * 16 + lrow;
    const int lane = t & 15;

    float4 acc = make_float4(0.f, 0.f, 0.f, 0.f);
    if (row < NN) acc = csr_row_acc_h(dense, row, lane);
    *reinterpret_cast<float4*>(&hs[lrow][lane * 4]) = acc;
    __syncthreads();

    const int w = t >> 5, lane32 = t & 31;
    const int j2 = lane32 + 32;
    const int j2c = (j2 < NC) ? j2 : 0;

    for (int rr = w; rr < 16; rr += 8) {
        int node = blockIdx.x * 16 + rr;
        if (node >= NN) continue;

        float l1 = bcs[lane32];
        float l2 = bcs[j2c];
#pragma unroll 8
        for (int k = 0; k < HID; k++) {
            float h = hs[rr][k];
            l1 += h * Wcs[k * NC + lane32];
            l2 += h * Wcs[k * NC + j2c];
        }
        if (j2 >= NC) l2 = -INFINITY;

        float m = fmaxf(l1, l2);
#pragma unroll
        for (int o = 16; o; o >>= 1) m = fmaxf(m, __shfl_xor_sync(0xffffffffu, m, o));
        float s = expf(l1 - m) + ((j2 < NC) ? expf(l2 - m) : 0.f);
#pragma unroll
        for (int o = 16; o; o >>= 1) s += __shfl_xor_sync(0xffffffffu, s, o);
        float lse = m + logf(s);

        out[(size_t)node * NC + lane32] = l1 - lse;
        if (j2 < NC) out[(size_t)node * NC + j2] = l2 - lse;
    }
}

// ---------------------------------------------------------------------------
extern "C" void kernel_launch(void* const* d_in, const int* in_sizes, int n_in,
                              void* d_out, int out_size) {
    const float* x  = (const float*)d_in[0];
    const int*   er = (const int*)d_in[1];
    const int*   ec = (const int*)d_in[2];
    const float* ev = (const float*)d_in[3];
    const float* W1 = (const float*)d_in[4];
    const float* b1 = (const float*)d_in[5];
    const float* W2 = (const float*)d_in[6];
    const float* b2 = (const float*)d_in[7];
    const float* Wc = (const float*)d_in[8];
    const float* bc = (const float*)d_in[9];
    float* out = (float*)d_out;

    __half *hA, *hB;
    cudaGetSymbolAddress((void**)&hA, g_hA);
    cudaGetSymbolAddress((void**)&hB, g_hB);
    int* offp;
    cudaGetSymbolAddress((void**)&offp, g_off);

    // One-time resource init (streams/events only; identical GPU work each call).
    static cudaStream_t sB = nullptr;
    static cudaEvent_t evFork = nullptr, evJoin = nullptr;
    if (sB == nullptr) {
        cudaStreamCreateWithFlags(&sB, cudaStreamNonBlocking);
        cudaEventCreateWithFlags(&evFork, cudaEventDisableTiming);
        cudaEventCreateWithFlags(&evJoin, cudaEventDisableTiming);
    }

    const int node_grid  = (NN + 255) / 256;             // 391
    const int edge4_grid = (NE / 4 + 255) / 256;         // 1563
    const int gemm_grid  = (NN + 127) / 128;             // 782
    const int spmm_grid  = (NN + 15) / 16;               // 6250

    // --- Fork: CSR build on side stream, gemm1 on capture stream ---
    cudaEventRecord(evFork, 0);
    cudaStreamWaitEvent(sB, evFork, 0);

    cudaMemsetAsync(offp, 0, (size_t)(NN + 1) * sizeof(int), sB);
    hist_kernel<<<edge4_grid, 256, 0, sB>>>((const int4*)er);
    scan1_kernel<<<NB, SCAN_BS, 0, sB>>>();
    scan3_kernel<<<node_grid, 256, 0, sB>>>();
    scatter_kernel<<<edge4_grid, 256, 0, sB>>>((const int4*)er, (const int4*)ec,
                                               (const float4*)ev);
    cudaEventRecord(evJoin, sB);

    // Layer 1 GEMM overlaps the build: support1 = x@W1+b1 (half out)
    gemm128_kernel<IND, false, false><<<gemm_grid, 256>>>(x, W1, b1, hA);

    // --- Join: spmm1 needs both CSR and support1 ---
    cudaStreamWaitEvent(0, evJoin, 0);
    spmm_csr_kernel<<<spmm_grid, 256>>>(hA, hB);

    // --- Layer 2: support2 = relu(h1)@W2+b2 ; out = cls(spmm(support2)) ---
    gemm128_kernel<HID, true, true><<<gemm_grid, 256>>>(hB, W2, b2, hA);
    spmm_cls_kernel<<<spmm_grid, 256>>>(hA, Wc, bc, out);
}

// round 12
// speedup vs baseline: 1.5120x; 1.0186x over previous
#include <cuda_runtime.h>
#include <cuda_fp16.h>
#include <math.h>

#define NN 100000
#define NE 1600000
#define IND 128
#define HID 64
#define NC 40
#define SCAN_BS 1024
#define NB 98              // ceil(NN/1024)

// Scratch (allocation-free per harness rules)
__device__ __half g_hA[(size_t)NN * HID];   // half intermediates (12.8 MB each)
__device__ __half g_hB[(size_t)NN * HID];
__device__ int    g_off[NN + 1];
__device__ int    g_pos[NN];
__device__ int    g_bsum[NB];
__device__ int4   g_epack4[NE / 2];         // packed edges, 16B-aligned base

// ---------------------------------------------------------------------------
// CSR build
// ---------------------------------------------------------------------------
__global__ __launch_bounds__(256) void hist_kernel(const int4* __restrict__ er4) {
    int i = blockIdx.x * 256 + threadIdx.x;
    if (i >= NE / 4) return;
    int4 r = __ldg(er4 + i);
    atomicAdd(&g_off[r.x], 1);
    atomicAdd(&g_off[r.y], 1);
    atomicAdd(&g_off[r.z], 1);
    atomicAdd(&g_off[r.w], 1);
}

__global__ __launch_bounds__(SCAN_BS) void scan1_kernel() {
    __shared__ int s[SCAN_BS];
    int i = blockIdx.x * SCAN_BS + threadIdx.x;
    int v = (i < NN) ? g_off[i] : 0;
    s[threadIdx.x] = v;
    __syncthreads();
#pragma unroll
    for (int o = 1; o < SCAN_BS; o <<= 1) {
        int t = (threadIdx.x >= o) ? s[threadIdx.x - o] : 0;
        __syncthreads();
        s[threadIdx.x] += t;
        __syncthreads();
    }
    if (i < NN) g_off[i] = s[threadIdx.x] - v;   // exclusive within block
    if (threadIdx.x == SCAN_BS - 1) g_bsum[blockIdx.x] = s[SCAN_BS - 1];
}

// Fused: each block redundantly scans the 98 block sums in smem, then applies.
__global__ __launch_bounds__(256) void scan3_kernel() {
    __shared__ int s[128];
    const int tid = threadIdx.x;
    int v = 0;
    if (tid < 128) {
        v = (tid < NB) ? g_bsum[tid] : 0;
        s[tid] = v;
    }
    __syncthreads();
#pragma unroll
    for (int o = 1; o < 128; o <<= 1) {
        int t = (tid < 128 && tid >= o) ? s[tid - o] : 0;
        __syncthreads();
        if (tid < 128) s[tid] += t;
        __syncthreads();
    }
    if (tid < 128) s[tid] -= v;   // exclusive block offsets
    __syncthreads();

    int i = blockIdx.x * 256 + tid;
    if (i < NN) {
        int o = g_off[i] + s[i >> 10];
        g_off[i] = o;
        g_pos[i] = o;
    }
    if (i == 0) g_off[NN] = NE;
}

// ILP-4 scatter: 4 independent atomic->store chains per thread.
__global__ __launch_bounds__(256) void scatter_kernel(
    const int4* __restrict__ er4, const int4* __restrict__ ec4,
    const float4* __restrict__ ev4) {
    int i = blockIdx.x * 256 + threadIdx.x;
    if (i >= NE / 4) return;
    int4 r = __ldg(er4 + i);
    int4 c = __ldg(ec4 + i);
    float4 v = __ldg(ev4 + i);
    int2* ep = (int2*)g_epack4;
    int p0 = atomicAdd(&g_pos[r.x], 1);
    int p1 = atomicAdd(&g_pos[r.y], 1);
    int p2 = atomicAdd(&g_pos[r.z], 1);
    int p3 = atomicAdd(&g_pos[r.w], 1);
    ep[p0] = make_int2(c.x, __float_as_int(v.x));
    ep[p1] = make_int2(c.y, __float_as_int(v.y));
    ep[p2] = make_int2(c.z, __float_as_int(v.z));
    ep[p3] = make_int2(c.w, __float_as_int(v.w));
}

// ---------------------------------------------------------------------------
// GEMM: C[NN,64](half) = act(A)[NN,K] @ W[K,64] + bias
// ---------------------------------------------------------------------------
template <int K, bool RELU, bool HIN>
__global__ __launch_bounds__(256) void gemm128_kernel(
    const void* __restrict__ Av, const float* __restrict__ W,
    const float* __restrict__ bias, __half* __restrict__ C) {
    __shared__ float As[128][36];
    __shared__ float Ws[32][64];

    const int t  = threadIdx.x;
    const int tx = t & 15;
    const int ty = t >> 4;
    const int row0 = blockIdx.x * 128;

    float acc[8][4];
#pragma unroll
    for (int i = 0; i < 8; i++)
#pragma unroll
        for (int j = 0; j < 4; j++) acc[i][j] = 0.f;

    for (int kt = 0; kt < K; kt += 32) {
#pragma unroll
        for (int u = 0; u < 4; u++) {
            int f = t + u * 256;
            int r = f >> 3;
            int kc = (f & 7) << 2;
            int grow = row0 + r;
            float4 v = make_float4(0.f, 0.f, 0.f, 0.f);
            if (grow < NN) {
                if (HIN) {
                    const __half* A = (const __half*)Av;
                    uint2 raw = __ldg(reinterpret_cast<const uint2*>(
                        A + (size_t)grow * K + kt + kc));
                    float2 f0 = __half22float2(*reinterpret_cast<__half2*>(&raw.x));
                    float2 f1 = __half22float2(*reinterpret_cast<__half2*>(&raw.y));
                    v = make_float4(f0.x, f0.y, f1.x, f1.y);
                } else {
                    const float* A = (const float*)Av;
                    v = *reinterpret_cast<const float4*>(A + (size_t)grow * K + kt + kc);
                }
            }
            if (RELU) {
                v.x = fmaxf(v.x, 0.f); v.y = fmaxf(v.y, 0.f);
                v.z = fmaxf(v.z, 0.f); v.w = fmaxf(v.w, 0.f);
            }
            *reinterpret_cast<float4*>(&As[r][kc]) = v;
        }
#pragma unroll
        for (int u = 0; u < 2; u++) {
            int f = t + u * 256;
            int r = f >> 4;
            int c = (f & 15) << 2;
            *reinterpret_cast<float4*>(&Ws[r][c]) =
                *reinterpret_cast<const float4*>(W + (size_t)(kt + r) * 64 + c);
        }
        __syncthreads();

#pragma unroll
        for (int kk = 0; kk < 32; kk += 4) {
            float4 a[8];
#pragma unroll
            for (int i = 0; i < 8; i++)
                a[i] = *reinterpret_cast<const float4*>(&As[(ty << 3) + i][kk]);
#pragma unroll
            for (int j = 0; j < 4; j++) {
                float4 b = *reinterpret_cast<const float4*>(&Ws[kk + j][tx << 2]);
#pragma unroll
                for (int i = 0; i < 8; i++) {
                    float s = (j == 0) ? a[i].x : (j == 1) ? a[i].y
                            : (j == 2) ? a[i].z : a[i].w;
                    acc[i][0] += s * b.x; acc[i][1] += s * b.y;
                    acc[i][2] += s * b.z; acc[i][3] += s * b.w;
                }
            }
        }
        __syncthreads();
    }

    float4 bv = *reinterpret_cast<const float4*>(bias + (tx << 2));
#pragma unroll
    for (int i = 0; i < 8; i++) {
        int grow = row0 + (ty << 3) + i;
        if (grow < NN) {
            __half2 o01 = __floats2half2_rn(acc[i][0] + bv.x, acc[i][1] + bv.y);
            __half2 o23 = __floats2half2_rn(acc[i][2] + bv.z, acc[i][3] + bv.w);
            uint2 st;
            st.x = *reinterpret_cast<unsigned*>(&o01);
            st.y = *reinterpret_cast<unsigned*>(&o23);
            *reinterpret_cast<uint2*>(C + (size_t)grow * 64 + (tx << 2)) = st;
        }
    }
}

// ---------------------------------------------------------------------------
// CSR SpMM gather: 8 threads/row, 16B dense slices, int4 epack (2 edges/load).
// ---------------------------------------------------------------------------
struct Acc8 { float4 lo, hi; };

__device__ __forceinline__ void acc_edge(Acc8& a, const __half* __restrict__ base,
                                         int c, float v) {
    uint4 r = __ldg(reinterpret_cast<const uint4*>(base + (size_t)c * HID));
    float2 f0 = __half22float2(*reinterpret_cast<__half2*>(&r.x));
    float2 f1 = __half22float2(*reinterpret_cast<__half2*>(&r.y));
    float2 f2 = __half22float2(*reinterpret_cast<__half2*>(&r.z));
    float2 f3 = __half22float2(*reinterpret_cast<__half2*>(&r.w));
    a.lo.x += v * f0.x; a.lo.y += v * f0.y;
    a.lo.z += v * f1.x; a.lo.w += v * f1.y;
    a.hi.x += v * f2.x; a.hi.y += v * f2.y;
    a.hi.z += v * f3.x; a.hi.w += v * f3.y;
}

__device__ __forceinline__ Acc8 csr_row_acc8(const __half* __restrict__ dense,
                                             int row, int lane) {
    int s = __ldg(g_off + row), e = __ldg(g_off + row + 1);
    const __half* base = dense + lane * 8;
    const int2* ep2 = (const int2*)g_epack4;
    Acc8 a;
    a.lo = make_float4(0.f, 0.f, 0.f, 0.f);
    a.hi = make_float4(0.f, 0.f, 0.f, 0.f);
    int i = s;
    if ((i & 1) && i < e) {               // peel to even index for int4 loads
        int2 e0 = __ldg(ep2 + i);
        acc_edge(a, base, e0.x, __int_as_float(e0.y));
        i++;
    }
    for (; i + 4 <= e; i += 4) {
        int4 p0 = __ldg(g_epack4 + (i >> 1));
        int4 p1 = __ldg(g_epack4 + (i >> 1) + 1);
        acc_edge(a, base, p0.x, __int_as_float(p0.y));
        acc_edge(a, base, p0.z, __int_as_float(p0.w));
        acc_edge(a, base, p1.x, __int_as_float(p1.y));
        acc_edge(a, base, p1.z, __int_as_float(p1.w));
    }
    for (; i < e; i++) {
        int2 e0 = __ldg(ep2 + i);
        acc_edge(a, base, e0.x, __int_as_float(e0.y));
    }
    return a;
}

__global__ __launch_bounds__(256) void spmm_csr_kernel(
    const __half* __restrict__ dense, __half* __restrict__ out) {
    int row = blockIdx.x * 32 + (threadIdx.x >> 3);
    if (row >= NN) return;
    int lane = threadIdx.x & 7;
    Acc8 a = csr_row_acc8(dense, row, lane);
    __half2 h0 = __floats2half2_rn(a.lo.x, a.lo.y);
    __half2 h1 = __floats2half2_rn(a.lo.z, a.lo.w);
    __half2 h2 = __floats2half2_rn(a.hi.x, a.hi.y);
    __half2 h3 = __floats2half2_rn(a.hi.z, a.hi.w);
    uint4 st;
    st.x = *reinterpret_cast<unsigned*>(&h0);
    st.y = *reinterpret_cast<unsigned*>(&h1);
    st.z = *reinterpret_cast<unsigned*>(&h2);
    st.w = *reinterpret_cast<unsigned*>(&h3);
    *reinterpret_cast<uint4*>(out + (size_t)row * HID + lane * 8) = st;
}

// ---------------------------------------------------------------------------
// Fused: h2 = spmm(dense) ; out = log_softmax(h2 @ Wc + bc)  (fp32 math)
// 32 rows per block.
// ---------------------------------------------------------------------------
__global__ __launch_bounds__(256) void spmm_cls_kernel(
    const __half* __restrict__ dense, const float* __restrict__ Wc,
    const float* __restrict__ bc, float* __restrict__ out) {
    __shared__ float hs[32][72];
    __shared__ float Wcs[HID * NC];
    __shared__ float bcs[NC];

    const int t = threadIdx.x;
    for (int i = t; i < HID * NC; i += 256) Wcs[i] = Wc[i];
    if (t < NC) bcs[t] = bc[t];

    const int lrow = t >> 3;
    const int row = blockIdx.x * 32 + lrow;
    const int lane = t & 7;

    Acc8 a;
    a.lo = make_float4(0.f, 0.f, 0.f, 0.f);
    a.hi = make_float4(0.f, 0.f, 0.f, 0.f);
    if (row < NN) a = csr_row_acc8(dense, row, lane);
    *reinterpret_cast<float4*>(&hs[lrow][lane * 8])     = a.lo;
    *reinterpret_cast<float4*>(&hs[lrow][lane * 8 + 4]) = a.hi;
    __syncthreads();

    const int w = t >> 5, lane32 = t & 31;
    const int j2 = lane32 + 32;
    const int j2c = (j2 < NC) ? j2 : 0;

    for (int rr = w; rr < 32; rr += 8) {
        int node = blockIdx.x * 32 + rr;
        if (node >= NN) continue;

        float l1 = bcs[lane32];
        float l2 = bcs[j2c];
#pragma unroll 8
        for (int k = 0; k < HID; k++) {
            float h = hs[rr][k];
            l1 += h * Wcs[k * NC + lane32];
            l2 += h * Wcs[k * NC + j2c];
        }
        if (j2 >= NC) l2 = -INFINITY;

        float m = fmaxf(l1, l2);
#pragma unroll
        for (int o = 16; o; o >>= 1) m = fmaxf(m, __shfl_xor_sync(0xffffffffu, m, o));
        float s = expf(l1 - m) + ((j2 < NC) ? expf(l2 - m) : 0.f);
#pragma unroll
        for (int o = 16; o; o >>= 1) s += __shfl_xor_sync(0xffffffffu, s, o);
        float lse = m + logf(s);

        out[(size_t)node * NC + lane32] = l1 - lse;
        if (j2 < NC) out[(size_t)node * NC + j2] = l2 - lse;
    }
}

// ---------------------------------------------------------------------------
extern "C" void kernel_launch(void* const* d_in, const int* in_sizes, int n_in,
                              void* d_out, int out_size) {
    const float* x  = (const float*)d_in[0];
    const int*   er = (const int*)d_in[1];
    const int*   ec = (const int*)d_in[2];
    const float* ev = (const float*)d_in[3];
    const float* W1 = (const float*)d_in[4];
    const float* b1 = (const float*)d_in[5];
    const float* W2 = (const float*)d_in[6];
    const float* b2 = (const float*)d_in[7];
    const float* Wc = (const float*)d_in[8];
    const float* bc = (const float*)d_in[9];
    float* out = (float*)d_out;

    __half *hA, *hB;
    cudaGetSymbolAddress((void**)&hA, g_hA);
    cudaGetSymbolAddress((void**)&hB, g_hB);
    int* offp;
    cudaGetSymbolAddress((void**)&offp, g_off);

    // One-time resource init (streams/events only; identical GPU work each call).
    static cudaStream_t sB = nullptr;
    static cudaEvent_t evFork = nullptr, evJoin = nullptr;
    if (sB == nullptr) {
        cudaStreamCreateWithFlags(&sB, cudaStreamNonBlocking);
        cudaEventCreateWithFlags(&evFork, cudaEventDisableTiming);
        cudaEventCreateWithFlags(&evJoin, cudaEventDisableTiming);
    }

    const int node_grid  = (NN + 255) / 256;             // 391
    const int edge4_grid = (NE / 4 + 255) / 256;         // 1563
    const int gemm_grid  = (NN + 127) / 128;             // 782
    const int spmm_grid  = (NN + 31) / 32;               // 3125

    // --- Fork: CSR build on side stream, gemm1 on capture stream ---
    cudaEventRecord(evFork, 0);
    cudaStreamWaitEvent(sB, evFork, 0);

    cudaMemsetAsync(offp, 0, (size_t)(NN + 1) * sizeof(int), sB);
    hist_kernel<<<edge4_grid, 256, 0, sB>>>((const int4*)er);
    scan1_kernel<<<NB, SCAN_BS, 0, sB>>>();
    scan3_kernel<<<node_grid, 256, 0, sB>>>();
    scatter_kernel<<<edge4_grid, 256, 0, sB>>>((const int4*)er, (const int4*)ec,
                                               (const float4*)ev);
    cudaEventRecord(evJoin, sB);

    // Layer 1 GEMM overlaps the build: support1 = x@W1+b1 (half out)
    gemm128_kernel<IND, false, false><<<gemm_grid, 256>>>(x, W1, b1, hA);

    // --- Join: spmm1 needs both CSR and support1 ---
    cudaStreamWaitEvent(0, evJoin, 0);
    spmm_csr_kernel<<<spmm_grid, 256>>>(hA, hB);

    // --- Layer 2: support2 = relu(h1)@W2+b2 ; out = cls(spmm(support2)) ---
    gemm128_kernel<HID, true, true><<<gemm_grid, 256>>>(hB, W2, b2, hA);
    spmm_cls_kernel<<<spmm_grid, 256>>>(hA, Wc, bc, out);
}